// round 2
// baseline (speedup 1.0000x reference)
#include <cuda_runtime.h>
#include <math.h>
#include <stdint.h>

#define T_STEPS 1024
#define BATCH   64
#define VDIM    256
#define HIDDEN  512
#define REC_BLOCKS 128
#define REC_THREADS 256
#define REC_SMEM ((HIDDEN*BATCH + 4*HIDDEN) * 4)

// Scratch (device globals: allocation APIs are forbidden)
__device__ float g_P [(size_t)T_STEPS * BATCH * HIDDEN];   // input projections (pre-activations)
__device__ float g_S0[(size_t)T_STEPS * BATCH * HIDDEN];   // layer-0 states
__device__ float g_Hbuf[2][HIDDEN * BATCH];                // double-buffered h, transposed [k][b]
__device__ unsigned g_bar_count;                            // grid barrier state (self-resetting)
__device__ unsigned g_bar_gen;

// ---------------------------------------------------------------------------
// GEMM: C[m][n] = sum_k A[m][k] * W[n*ldw + k] + bias[n],  C row stride = HIDDEN
// BM=BN=128, BK=8, 256 threads, 8x8 micro-tile.
// M = 65536 (mult of 128), N = 512 (mult of 128), K mult of 8.
// ---------------------------------------------------------------------------
__global__ __launch_bounds__(256) void gemm_awt(
    const float* __restrict__ A, const float* __restrict__ W,
    const float* __restrict__ bias, float* __restrict__ C,
    int K, int ldw)
{
    __shared__ float As[8][128];
    __shared__ float Ws[8][128];

    const int tid = threadIdx.x;
    const int m0 = blockIdx.y * 128;
    const int n0 = blockIdx.x * 128;
    const int tx = tid & 15;        // n direction
    const int ty = tid >> 4;        // m direction

    const int rowL = tid >> 1;           // 0..127
    const int colL = (tid & 1) * 4;      // 0 or 4

    const float* Ag = A + (size_t)(m0 + rowL) * K + colL;
    const float* Wg = W + (size_t)(n0 + rowL) * ldw + colL;

    float acc[8][8];
#pragma unroll
    for (int i = 0; i < 8; ++i)
#pragma unroll
        for (int j = 0; j < 8; ++j) acc[i][j] = 0.f;

    for (int k0 = 0; k0 < K; k0 += 8) {
        float4 av = *(const float4*)(Ag + k0);
        float4 wv = *(const float4*)(Wg + k0);
        __syncthreads();
        As[colL + 0][rowL] = av.x; As[colL + 1][rowL] = av.y;
        As[colL + 2][rowL] = av.z; As[colL + 3][rowL] = av.w;
        Ws[colL + 0][rowL] = wv.x; Ws[colL + 1][rowL] = wv.y;
        Ws[colL + 2][rowL] = wv.z; Ws[colL + 3][rowL] = wv.w;
        __syncthreads();
#pragma unroll
        for (int k = 0; k < 8; ++k) {
            float a[8], b[8];
#pragma unroll
            for (int i = 0; i < 8; ++i) a[i] = As[k][ty * 8 + i];
#pragma unroll
            for (int j = 0; j < 8; ++j) b[j] = Ws[k][tx * 8 + j];
#pragma unroll
            for (int i = 0; i < 8; ++i)
#pragma unroll
                for (int j = 0; j < 8; ++j)
                    acc[i][j] += a[i] * b[j];
        }
    }

    float bn[8];
#pragma unroll
    for (int j = 0; j < 8; ++j) bn[j] = bias[n0 + tx * 8 + j];

    float* Cp = C + (size_t)(m0 + ty * 8) * HIDDEN + n0 + tx * 8;
#pragma unroll
    for (int i = 0; i < 8; ++i) {
        float4 v0, v1;
        v0.x = acc[i][0] + bn[0]; v0.y = acc[i][1] + bn[1];
        v0.z = acc[i][2] + bn[2]; v0.w = acc[i][3] + bn[3];
        v1.x = acc[i][4] + bn[4]; v1.y = acc[i][5] + bn[5];
        v1.z = acc[i][6] + bn[6]; v1.w = acc[i][7] + bn[7];
        *(float4*)(Cp + (size_t)i * HIDDEN)     = v0;
        *(float4*)(Cp + (size_t)i * HIDDEN + 4) = v1;
    }
}

// ---------------------------------------------------------------------------
// Persistent recurrence kernel with software grid barrier.
// h_{t} = tanh(P[t] + h_{t-1} @ Wh^T)   (bias already folded into P)
// 128 blocks x 256 threads; block owns j in [4*bx, 4*bx+4), all 64 batches.
// Wh rows live in smem for the entire scan; H (transposed [k][b], 128KB)
// staged per step.
// ---------------------------------------------------------------------------
__device__ __forceinline__ void grid_barrier(unsigned nb)
{
    __threadfence();
    __syncthreads();
    if (threadIdx.x == 0) {
        unsigned gen = atomicAdd(&g_bar_gen, 0u);
        unsigned ticket = atomicAdd(&g_bar_count, 1u);
        if (ticket == nb - 1u) {
            atomicExch(&g_bar_count, 0u);
            __threadfence();
            atomicAdd(&g_bar_gen, 1u);
        } else {
            while (atomicAdd(&g_bar_gen, 0u) == gen) { }
        }
    }
    __syncthreads();
}

__global__ __launch_bounds__(REC_THREADS, 1) void rnn_rec(
    const float* __restrict__ P,       // [T][B][HID] pre-activations (bias included)
    const float* __restrict__ Wfull,   // weight matrix rows [HID][ldw]
    int ldw, int koff,                 // Wh[j][k] = Wfull[j*ldw + koff + k]
    const float* __restrict__ h0,      // [B][HID]
    float* __restrict__ states,        // [T][B][HID]
    float* __restrict__ last,          // [B][HID]
    unsigned nb)
{
    extern __shared__ float sh[];
    float* Hs  = sh;                   // [HID][BATCH] transposed h  (32768 floats)
    float* Whs = sh + HIDDEN * BATCH;  // [4][HID] this block's Wh rows

    const int tid = threadIdx.x;
    const int j0  = blockIdx.x * 4;
    const int b   = tid & 63;
    const int g   = tid >> 6;          // 0..3
    const int j   = j0 + g;

    // Load this block's 4 Wh rows once.
    for (int idx = tid; idx < 4 * HIDDEN; idx += REC_THREADS) {
        int gg = idx >> 9, k = idx & 511;
        Whs[idx] = Wfull[(size_t)(j0 + gg) * ldw + koff + k];
    }

    for (int t = 0; t < T_STEPS; ++t) {
        // Stage h_{t-1} into smem, transposed [k][b].
        if (t == 0) {
            for (int i = tid; i < HIDDEN * BATCH; i += REC_THREADS) {
                int bb = i >> 9, k = i & 511;
                Hs[k * BATCH + bb] = h0[i];
            }
        } else {
            const float4* src = (const float4*)g_Hbuf[(t - 1) & 1];
            float4* dst = (float4*)Hs;
            for (int i = tid; i < HIDDEN * BATCH / 4; i += REC_THREADS)
                dst[i] = __ldcg(src + i);   // bypass L1: written by other SMs
        }
        __syncthreads();

        float acc = P[((size_t)t * BATCH + b) * HIDDEN + j];
        const float4* w4 = (const float4*)(Whs + g * HIDDEN);
        const float* hb = Hs + b;
#pragma unroll 8
        for (int k4 = 0; k4 < HIDDEN / 4; ++k4) {
            float4 w = w4[k4];
            int base = k4 * 4 * BATCH;
            acc += hb[base]             * w.x;
            acc += hb[base +     BATCH] * w.y;
            acc += hb[base + 2 * BATCH] * w.z;
            acc += hb[base + 3 * BATCH] * w.w;
        }
        float h = tanhf(acc);

        g_Hbuf[t & 1][j * BATCH + b] = h;                     // coalesced
        states[((size_t)t * BATCH + b) * HIDDEN + j] = h;
        if (t == T_STEPS - 1) last[(size_t)b * HIDDEN + j] = h;

        grid_barrier(nb);   // includes fence + syncthreads (also guards Hs reuse)
    }
}

// ---------------------------------------------------------------------------
extern "C" void kernel_launch(void* const* d_in, const int* in_sizes, int n_in,
                              void* d_out, int out_size)
{
    (void)in_sizes; (void)n_in; (void)out_size;
    const float* inputs = (const float*)d_in[0];   // [T][B][V]
    const float* H      = (const float*)d_in[1];   // [L][B][HID]
    const float* W_net  = (const float*)d_in[2];   // [HID][V+HID]
    const float* b_net  = (const float*)d_in[3];   // [HID]
    const float* W_deep = (const float*)d_in[4];   // [HID][2*HID]
    const float* b_deep = (const float*)d_in[5];   // [HID]

    float* out     = (float*)d_out;
    float* states1 = out;                                        // [T][B][HID]
    float* lasts   = out + (size_t)T_STEPS * BATCH * HIDDEN;     // [L][B][HID]

    float *P, *S0;
    cudaGetSymbolAddress((void**)&P,  g_P);
    cudaGetSymbolAddress((void**)&S0, g_S0);

    cudaFuncSetAttribute(rnn_rec, cudaFuncAttributeMaxDynamicSharedMemorySize, REC_SMEM);

    dim3 ggrid(HIDDEN / 128, (T_STEPS * BATCH) / 128);  // (4, 512)

    // Layer 0
    gemm_awt<<<ggrid, 256>>>(inputs, W_net, b_net, P, VDIM, VDIM + HIDDEN);
    rnn_rec<<<REC_BLOCKS, REC_THREADS, REC_SMEM>>>(
        P, W_net, VDIM + HIDDEN, VDIM, H, S0, lasts, REC_BLOCKS);

    // Layer 1
    gemm_awt<<<ggrid, 256>>>(S0, W_deep, b_deep, P, HIDDEN, 2 * HIDDEN);
    rnn_rec<<<REC_BLOCKS, REC_THREADS, REC_SMEM>>>(
        P, W_deep, 2 * HIDDEN, HIDDEN, H + BATCH * HIDDEN, states1,
        lasts + BATCH * HIDDEN, REC_BLOCKS);
}

// round 3
// speedup vs baseline: 1.0284x; 1.0284x over previous
#include <cuda_runtime.h>
#include <math.h>
#include <stdint.h>

#define T_STEPS 1024
#define BATCH   64
#define VDIM    256
#define HIDDEN  512
#define NB      128          // recurrence blocks (1 per SM, 4 columns each)
#define RT      256          // recurrence threads
#define REC_SMEM ((HIDDEN*BATCH + 4*HIDDEN) * 4)   // 136 KB

// Scratch (device globals: allocation APIs are forbidden)
__device__ float g_P [(size_t)T_STEPS * BATCH * HIDDEN];
__device__ float g_S0[(size_t)T_STEPS * BATCH * HIDDEN];
__device__ float g_Hbuf[2][HIDDEN * BATCH];     // double-buffered h, [k][b]

struct PadU { unsigned v; unsigned pad[63]; };  // own 256B line each
__device__ PadU g_count;
__device__ PadU g_gen;

// ---------------------------------------------------------------------------
// helpers
// ---------------------------------------------------------------------------
__device__ __forceinline__ unsigned smem_u32(const void* p) {
    return (unsigned)__cvta_generic_to_shared(p);
}
__device__ __forceinline__ void cp16(unsigned s, const void* g) {
    asm volatile("cp.async.cg.shared.global [%0], [%1], 16;" :: "r"(s), "l"(g));
}
#define CP_COMMIT() asm volatile("cp.async.commit_group;")

// dot over one 128-k chunk: thread owns (j, b); w broadcast per warp, h conflict-free
__device__ __forceinline__ float chunk_dot(const float* __restrict__ Hs,
                                           const float4* __restrict__ w4,
                                           int b, int c)
{
    float acc = 0.f;
    const float* hb = Hs + c * 128 * BATCH + b;
#pragma unroll
    for (int k4 = 0; k4 < 32; ++k4) {
        float4 w = w4[c * 32 + k4];
        int base = k4 * 4 * BATCH;
        acc += hb[base]             * w.x;
        acc += hb[base +     BATCH] * w.y;
        acc += hb[base + 2 * BATCH] * w.z;
        acc += hb[base + 3 * BATCH] * w.w;
    }
    return acc;
}

// ---------------------------------------------------------------------------
// GEMM: C[m][n] = sum_k A[m][k]*W[n*ldw+k] + bias[n], C row stride = HIDDEN
// BM=BN=128, BK=8, 256 threads, 8x8 micro-tile, register prefetch of next slab.
// ---------------------------------------------------------------------------
__global__ __launch_bounds__(256) void gemm_awt(
    const float* __restrict__ A, const float* __restrict__ W,
    const float* __restrict__ bias, float* __restrict__ C,
    int K, int ldw)
{
    __shared__ float As[8][128];
    __shared__ float Ws[8][128];

    const int tid = threadIdx.x;
    const int m0 = blockIdx.y * 128;
    const int n0 = blockIdx.x * 128;
    const int tx = tid & 15;
    const int ty = tid >> 4;
    const int rowL = tid >> 1;
    const int colL = (tid & 1) * 4;

    const float* Ag = A + (size_t)(m0 + rowL) * K + colL;
    const float* Wg = W + (size_t)(n0 + rowL) * ldw + colL;

    float acc[8][8];
#pragma unroll
    for (int i = 0; i < 8; ++i)
#pragma unroll
        for (int j = 0; j < 8; ++j) acc[i][j] = 0.f;

    float4 av = *(const float4*)(Ag);
    float4 wv = *(const float4*)(Wg);

    for (int k0 = 0; k0 < K; k0 += 8) {
        __syncthreads();
        As[colL + 0][rowL] = av.x; As[colL + 1][rowL] = av.y;
        As[colL + 2][rowL] = av.z; As[colL + 3][rowL] = av.w;
        Ws[colL + 0][rowL] = wv.x; Ws[colL + 1][rowL] = wv.y;
        Ws[colL + 2][rowL] = wv.z; Ws[colL + 3][rowL] = wv.w;
        __syncthreads();
        if (k0 + 8 < K) {                       // prefetch next slab
            av = *(const float4*)(Ag + k0 + 8);
            wv = *(const float4*)(Wg + k0 + 8);
        }
#pragma unroll
        for (int k = 0; k < 8; ++k) {
            float a[8], b[8];
#pragma unroll
            for (int i = 0; i < 8; ++i) a[i] = As[k][ty * 8 + i];
#pragma unroll
            for (int j = 0; j < 8; ++j) b[j] = Ws[k][tx * 8 + j];
#pragma unroll
            for (int i = 0; i < 8; ++i)
#pragma unroll
                for (int j = 0; j < 8; ++j)
                    acc[i][j] += a[i] * b[j];
        }
    }

    float bn[8];
#pragma unroll
    for (int j = 0; j < 8; ++j) bn[j] = bias[n0 + tx * 8 + j];

    float* Cp = C + (size_t)(m0 + ty * 8) * HIDDEN + n0 + tx * 8;
#pragma unroll
    for (int i = 0; i < 8; ++i) {
        float4 v0, v1;
        v0.x = acc[i][0] + bn[0]; v0.y = acc[i][1] + bn[1];
        v0.z = acc[i][2] + bn[2]; v0.w = acc[i][3] + bn[3];
        v1.x = acc[i][4] + bn[4]; v1.y = acc[i][5] + bn[5];
        v1.z = acc[i][6] + bn[6]; v1.w = acc[i][7] + bn[7];
        *(float4*)(Cp + (size_t)i * HIDDEN)     = v0;
        *(float4*)(Cp + (size_t)i * HIDDEN + 4) = v1;
    }
}

// ---------------------------------------------------------------------------
// Persistent recurrence: h_t = tanh(P[t] + h_{t-1} @ Wh^T)
// 128 blocks x 256 threads. Block owns 4 columns; Wh rows resident in smem.
// H staged per step via cp.async.cg in 4 pipelined 32KB chunks.
// Grid barrier: atomic ticket arrival + plain-load polling on a separate line.
// ---------------------------------------------------------------------------
__global__ __launch_bounds__(RT, 1) void rnn_rec(
    const float* __restrict__ P,
    const float* __restrict__ Wfull, int ldw, int koff,
    const float* __restrict__ h0,
    float* __restrict__ states,
    float* __restrict__ last)
{
    extern __shared__ float sh[];
    float* Hs  = sh;                   // [512][64]
    float* Whs = sh + HIDDEN * BATCH;  // [4][512]

    const int tid = threadIdx.x;
    const int j0  = blockIdx.x * 4;
    const int b   = tid & 63;
    const int g   = tid >> 6;
    const int j   = j0 + g;

    for (int idx = tid; idx < 4 * HIDDEN; idx += RT)
        Whs[idx] = Wfull[(size_t)(j0 + (idx >> 9)) * ldw + koff + (idx & 511)];

    // stage h0 transposed [k][b]
    for (int i = tid; i < HIDDEN * BATCH; i += RT) {
        int bb = i >> 9, k = i & 511;
        Hs[k * BATCH + bb] = h0[i];
    }
    __syncthreads();

    unsigned gen = *(volatile unsigned*)&g_gen.v;   // stable: no one increments yet
    const float4* w4 = (const float4*)(Whs + g * HIDDEN);
    const unsigned hs_s = smem_u32(Hs);

    for (int t = 0; t < T_STEPS; ++t) {
        float p = P[((size_t)t * BATCH + b) * HIDDEN + j];   // early LDG
        float acc = 0.f;

        if (t == 0) {
#pragma unroll
            for (int c = 0; c < 4; ++c) acc += chunk_dot(Hs, w4, b, c);
        } else {
            const float4* src = (const float4*)g_Hbuf[(t - 1) & 1];
            // prologue: chunk 0
#pragma unroll
            for (int i = 0; i < 8; ++i) {
                int idx = tid + i * RT;
                cp16(hs_s + idx * 16, (const void*)(src + idx));
            }
            CP_COMMIT();
#pragma unroll
            for (int c = 0; c < 4; ++c) {
                if (c < 3) {
#pragma unroll
                    for (int i = 0; i < 8; ++i) {
                        int idx = (c + 1) * 2048 + tid + i * RT;
                        cp16(hs_s + idx * 16, (const void*)(src + idx));
                    }
                    CP_COMMIT();
                    asm volatile("cp.async.wait_group 1;");
                } else {
                    asm volatile("cp.async.wait_group 0;");
                }
                __syncthreads();
                acc += chunk_dot(Hs, w4, b, c);
            }
        }

        float h = tanhf(p + acc);
        g_Hbuf[t & 1][(size_t)j * BATCH + b] = h;            // coalesced
        states[((size_t)t * BATCH + b) * HIDDEN + j] = h;
        if (t == T_STEPS - 1) last[(size_t)b * HIDDEN + j] = h;

        // ---- grid barrier: atomic arrive, plain-load poll ----
        __threadfence();
        __syncthreads();
        if (tid == 0) {
            unsigned tk = atomicAdd(&g_count.v, 1u);
            if (tk == NB - 1u) {
                *(volatile unsigned*)&g_count.v = 0u;
                __threadfence();
                *(volatile unsigned*)&g_gen.v = gen + 1u;    // release
            } else {
                while (*(volatile unsigned*)&g_gen.v == gen) { }
            }
            __threadfence();
        }
        __syncthreads();
        ++gen;
    }
}

// ---------------------------------------------------------------------------
extern "C" void kernel_launch(void* const* d_in, const int* in_sizes, int n_in,
                              void* d_out, int out_size)
{
    (void)in_sizes; (void)n_in; (void)out_size;
    const float* inputs = (const float*)d_in[0];
    const float* H      = (const float*)d_in[1];
    const float* W_net  = (const float*)d_in[2];
    const float* b_net  = (const float*)d_in[3];
    const float* W_deep = (const float*)d_in[4];
    const float* b_deep = (const float*)d_in[5];

    float* out     = (float*)d_out;
    float* states1 = out;
    float* lasts   = out + (size_t)T_STEPS * BATCH * HIDDEN;

    float *P, *S0;
    cudaGetSymbolAddress((void**)&P,  g_P);
    cudaGetSymbolAddress((void**)&S0, g_S0);

    cudaFuncSetAttribute(rnn_rec, cudaFuncAttributeMaxDynamicSharedMemorySize, REC_SMEM);

    dim3 ggrid(HIDDEN / 128, (T_STEPS * BATCH) / 128);

    gemm_awt<<<ggrid, 256>>>(inputs, W_net, b_net, P, VDIM, VDIM + HIDDEN);
    rnn_rec<<<NB, RT, REC_SMEM>>>(P, W_net, VDIM + HIDDEN, VDIM, H, S0, lasts);

    gemm_awt<<<ggrid, 256>>>(S0, W_deep, b_deep, P, HIDDEN, 2 * HIDDEN);
    rnn_rec<<<NB, RT, REC_SMEM>>>(P, W_deep, 2 * HIDDEN, HIDDEN,
                                  H + BATCH * HIDDEN, states1,
                                  lasts + BATCH * HIDDEN);
}

// round 4
// speedup vs baseline: 1.2430x; 1.2087x over previous
#include <cuda_runtime.h>
#include <math.h>
#include <stdint.h>

#define T_STEPS 1024
#define BATCH   64
#define VDIM    256
#define HIDDEN  512
#define CPB     64            // columns per block
#define BG      4             // batches per group
#define CBLKS   (HIDDEN / CPB)    // 8 column-blocks per group
#define GROUPS  (BATCH / BG)      // 16 independent batch groups
#define NB      (CBLKS * GROUPS)  // 128 blocks
#define RT      256
#define WPAD    516           // padded row stride (floats) for smem
#define REC_SMEM ((CPB * WPAD + BG * WPAD) * 4)   // ~137 KB

// Scratch (device globals: allocation APIs are forbidden)
__device__ float g_P [(size_t)T_STEPS * BATCH * HIDDEN];
__device__ float g_S0[(size_t)T_STEPS * BATCH * HIDDEN];
__device__ float g_Hbuf[2][GROUPS][BG * HIDDEN];   // per-group h, [b_loc][k]

struct PadU { unsigned v; unsigned pad[63]; };
__device__ PadU g_count[GROUPS];
__device__ PadU g_gen[GROUPS];

// ---------------------------------------------------------------------------
__device__ __forceinline__ unsigned smem_u32(const void* p) {
    return (unsigned)__cvta_generic_to_shared(p);
}
__device__ __forceinline__ void cp16(unsigned s, const void* g) {
    asm volatile("cp.async.cg.shared.global [%0], [%1], 16;" :: "r"(s), "l"(g));
}

// ---------------------------------------------------------------------------
// GEMM: C[m][n] = sum_k A[m][k]*W[n*ldw+k] + bias[n], C row stride = HIDDEN
// ---------------------------------------------------------------------------
__global__ __launch_bounds__(256) void gemm_awt(
    const float* __restrict__ A, const float* __restrict__ W,
    const float* __restrict__ bias, float* __restrict__ C,
    int K, int ldw)
{
    __shared__ float As[8][128];
    __shared__ float Ws[8][128];

    const int tid = threadIdx.x;
    const int m0 = blockIdx.y * 128;
    const int n0 = blockIdx.x * 128;
    const int tx = tid & 15;
    const int ty = tid >> 4;
    const int rowL = tid >> 1;
    const int colL = (tid & 1) * 4;

    const float* Ag = A + (size_t)(m0 + rowL) * K + colL;
    const float* Wg = W + (size_t)(n0 + rowL) * ldw + colL;

    float acc[8][8];
#pragma unroll
    for (int i = 0; i < 8; ++i)
#pragma unroll
        for (int j = 0; j < 8; ++j) acc[i][j] = 0.f;

    float4 av = *(const float4*)(Ag);
    float4 wv = *(const float4*)(Wg);

    for (int k0 = 0; k0 < K; k0 += 8) {
        __syncthreads();
        As[colL + 0][rowL] = av.x; As[colL + 1][rowL] = av.y;
        As[colL + 2][rowL] = av.z; As[colL + 3][rowL] = av.w;
        Ws[colL + 0][rowL] = wv.x; Ws[colL + 1][rowL] = wv.y;
        Ws[colL + 2][rowL] = wv.z; Ws[colL + 3][rowL] = wv.w;
        __syncthreads();
        if (k0 + 8 < K) {
            av = *(const float4*)(Ag + k0 + 8);
            wv = *(const float4*)(Wg + k0 + 8);
        }
#pragma unroll
        for (int k = 0; k < 8; ++k) {
            float a[8], b[8];
#pragma unroll
            for (int i = 0; i < 8; ++i) a[i] = As[k][ty * 8 + i];
#pragma unroll
            for (int j = 0; j < 8; ++j) b[j] = Ws[k][tx * 8 + j];
#pragma unroll
            for (int i = 0; i < 8; ++i)
#pragma unroll
                for (int j = 0; j < 8; ++j)
                    acc[i][j] += a[i] * b[j];
        }
    }

    float bn[8];
#pragma unroll
    for (int j = 0; j < 8; ++j) bn[j] = bias[n0 + tx * 8 + j];

    float* Cp = C + (size_t)(m0 + ty * 8) * HIDDEN + n0 + tx * 8;
#pragma unroll
    for (int i = 0; i < 8; ++i) {
        float4 v0, v1;
        v0.x = acc[i][0] + bn[0]; v0.y = acc[i][1] + bn[1];
        v0.z = acc[i][2] + bn[2]; v0.w = acc[i][3] + bn[3];
        v1.x = acc[i][4] + bn[4]; v1.y = acc[i][5] + bn[5];
        v1.z = acc[i][6] + bn[6]; v1.w = acc[i][7] + bn[7];
        *(float4*)(Cp + (size_t)i * HIDDEN)     = v0;
        *(float4*)(Cp + (size_t)i * HIDDEN + 4) = v1;
    }
}

// ---------------------------------------------------------------------------
// Persistent recurrence, batch-partitioned:
//   block = (col-block cblk, batch-group grp); owns 64 cols x 4 batches.
//   Wh[64 cols][512] resident in smem; h slice (8 KB) staged per step.
//   Sync only among the 8 col-blocks of the same group.
// ---------------------------------------------------------------------------
__global__ __launch_bounds__(RT, 1) void rnn_rec(
    const float* __restrict__ P,
    const float* __restrict__ Wfull, int ldw, int koff,
    const float* __restrict__ h0,
    float* __restrict__ states,
    float* __restrict__ last)
{
    extern __shared__ float sh[];
    float* Whs = sh;                     // [64][WPAD]
    float* Hs  = sh + CPB * WPAD;        // [4][WPAD]

    const int tid  = threadIdx.x;
    const int cblk = blockIdx.x & (CBLKS - 1);
    const int grp  = blockIdx.x >> 3;
    const int j0   = cblk * CPB;
    const int bl   = tid & (BG - 1);     // 0..3 local batch
    const int jl   = tid >> 2;           // 0..63 local column
    const int j    = j0 + jl;
    const int b    = grp * BG + bl;

    // Load this block's Wh rows (64 x 512) into padded smem.
    for (int idx = tid; idx < CPB * HIDDEN; idx += RT) {
        int r = idx >> 9, k = idx & 511;
        Whs[r * WPAD + k] = Wfull[(size_t)(j0 + r) * ldw + koff + k];
    }
    // Stage h0 for our 4 batches: Hs[bl][k].
    for (int i = tid; i < BG * HIDDEN; i += RT) {
        int bb = i >> 9, k = i & 511;
        Hs[bb * WPAD + k] = h0[(size_t)(grp * BG + bb) * HIDDEN + k];
    }
    __syncthreads();

    unsigned gen = *(volatile unsigned*)&g_gen[grp].v;
    const float4* wrow = (const float4*)(Whs + jl * WPAD);
    const float4* hrow = (const float4*)(Hs + bl * WPAD);
    const unsigned hs_s = smem_u32(Hs);
    float* hbase = &g_Hbuf[0][grp][0];
    float* hbase1 = &g_Hbuf[1][grp][0];

    for (int t = 0; t < T_STEPS; ++t) {
        // Stage h_{t-1} (written by our group last step) into Hs.
        if (t > 0) {
            const float4* src = (const float4*)((t & 1) ? hbase : hbase1);
#pragma unroll
            for (int u = 0; u < 2; ++u) {
                int i = tid + u * RT;            // 0..511 float4s
                int row = i >> 7, kk = i & 127;
                cp16(hs_s + (row * WPAD + kk * 4) * 4, src + row * 128 + kk);
            }
            asm volatile("cp.async.commit_group;");
        }

        float p = P[((size_t)t * BATCH + b) * HIDDEN + j];

        if (t > 0) {
            asm volatile("cp.async.wait_group 0;");
            __syncthreads();
        }

        // 512-long dot: float4 w x float4 h, 4 accumulators.
        float a0 = 0.f, a1 = 0.f, a2 = 0.f, a3 = 0.f;
#pragma unroll 8
        for (int k4 = 0; k4 < HIDDEN / 4; k4 += 4) {
            float4 w, h;
            w = wrow[k4];     h = hrow[k4];
            a0 += w.x * h.x; a0 += w.y * h.y; a0 += w.z * h.z; a0 += w.w * h.w;
            w = wrow[k4 + 1]; h = hrow[k4 + 1];
            a1 += w.x * h.x; a1 += w.y * h.y; a1 += w.z * h.z; a1 += w.w * h.w;
            w = wrow[k4 + 2]; h = hrow[k4 + 2];
            a2 += w.x * h.x; a2 += w.y * h.y; a2 += w.z * h.z; a2 += w.w * h.w;
            w = wrow[k4 + 3]; h = hrow[k4 + 3];
            a3 += w.x * h.x; a3 += w.y * h.y; a3 += w.z * h.z; a3 += w.w * h.w;
        }
        float hv = tanhf(p + (a0 + a1) + (a2 + a3));

        // Publish h for our group ([b_loc][k] layout) + outputs.
        ((t & 1) ? hbase1 : hbase)[bl * HIDDEN + j] = hv;
        states[((size_t)t * BATCH + b) * HIDDEN + j] = hv;
        if (t == T_STEPS - 1) last[(size_t)b * HIDDEN + j] = hv;

        // Group barrier (8 blocks): atomic arrive, plain-load poll.
        __threadfence();
        __syncthreads();
        if (tid == 0) {
            unsigned tk = atomicAdd(&g_count[grp].v, 1u);
            if (tk == CBLKS - 1u) {
                *(volatile unsigned*)&g_count[grp].v = 0u;
                __threadfence();
                *(volatile unsigned*)&g_gen[grp].v = gen + 1u;
            } else {
                while (*(volatile unsigned*)&g_gen[grp].v == gen) { }
            }
            __threadfence();
        }
        __syncthreads();
        ++gen;
    }
}

// ---------------------------------------------------------------------------
extern "C" void kernel_launch(void* const* d_in, const int* in_sizes, int n_in,
                              void* d_out, int out_size)
{
    (void)in_sizes; (void)n_in; (void)out_size;
    const float* inputs = (const float*)d_in[0];
    const float* H      = (const float*)d_in[1];
    const float* W_net  = (const float*)d_in[2];
    const float* b_net  = (const float*)d_in[3];
    const float* W_deep = (const float*)d_in[4];
    const float* b_deep = (const float*)d_in[5];

    float* out     = (float*)d_out;
    float* states1 = out;
    float* lasts   = out + (size_t)T_STEPS * BATCH * HIDDEN;

    float *P, *S0;
    cudaGetSymbolAddress((void**)&P,  g_P);
    cudaGetSymbolAddress((void**)&S0, g_S0);

    cudaFuncSetAttribute(rnn_rec, cudaFuncAttributeMaxDynamicSharedMemorySize, REC_SMEM);

    dim3 ggrid(HIDDEN / 128, (T_STEPS * BATCH) / 128);

    gemm_awt<<<ggrid, 256>>>(inputs, W_net, b_net, P, VDIM, VDIM + HIDDEN);
    rnn_rec<<<NB, RT, REC_SMEM>>>(P, W_net, VDIM + HIDDEN, VDIM, H, S0, lasts);

    gemm_awt<<<ggrid, 256>>>(S0, W_deep, b_deep, P, HIDDEN, 2 * HIDDEN);
    rnn_rec<<<NB, RT, REC_SMEM>>>(P, W_deep, 2 * HIDDEN, HIDDEN,
                                  H + BATCH * HIDDEN, states1,
                                  lasts + BATCH * HIDDEN);
}